// round 1
// baseline (speedup 1.0000x reference)
#include <cuda_runtime.h>
#include <cstdint>
#include <cstddef>

// Problem constants
#define BB 128
#define FF 512
#define TT 256
#define UU 1024

// Tiling
#define TM 128
#define TN 128
#define TK 16
#define NTHREADS 256

__device__ __forceinline__ unsigned long long splat2(float x) {
    unsigned long long r;
    asm("mov.b64 %0, {%1, %1};" : "=l"(r) : "f"(x));
    return r;
}

__device__ __forceinline__ void fma2(unsigned long long& d, unsigned long long a,
                                     unsigned long long b) {
    // packed 2x fp32 FMA (Blackwell): d = a*b + d  elementwise on (lo,hi)
    asm("fma.rn.f32x2 %0, %1, %2, %3;" : "=l"(d) : "l"(a), "l"(b), "l"(d));
}

__device__ __forceinline__ void lds_v2(unsigned long long& a, unsigned long long& b,
                                       unsigned addr) {
    asm volatile("ld.shared.v2.u64 {%0, %1}, [%2];" : "=l"(a), "=l"(b) : "r"(addr));
}

__device__ __forceinline__ float2 unpack2(unsigned long long v) {
    float2 r;
    asm("mov.b64 {%0, %1}, %2;" : "=f"(r.x), "=f"(r.y) : "l"(v));
    return r;
}

__global__ __launch_bounds__(NTHREADS)
void snn_gemm_kernel(const float* __restrict__ x,   // [B, F, T]
                     const float* __restrict__ w,   // [F, U]
                     float* __restrict__ out)       // [B, U, T]
{
    // C[u, t] = sum_f w[f, u] * x[b, f, t];  out = (C > 1) ? 1 : 0
    __shared__ float As[TK][TM];   // W chunk:  As[k][m] = w[f0+k][u0+m]
    __shared__ float Bs[TK][TN];   // X chunk (XOR-swizzled at float4-group granularity)

    const int tid = threadIdx.x;
    const int bz  = blockIdx.z;          // batch
    const int u0  = blockIdx.y * TM;
    const int t0  = blockIdx.x * TN;

    const int tx = tid & 15;             // t micro-tile (8 cols)
    const int ty = tid >> 4;             // u micro-tile (8 rows)
    const int ty8 = ty * 8;

    // ---- global loader mapping: 512 float4 slots per stage, 2 per thread ----
    const int lk = tid >> 5;             // k row 0..7 (second slot: +8)
    const int lc = tid & 31;             // float4 group within a 128-float row
    const int pc = lc ^ (lc >> 3);       // swizzled store group for Bs

    const float* wp = w + (size_t)lk * UU + u0 + lc * 4;
    const float* xp = x + (size_t)bz * FF * TT + (size_t)lk * TT + t0 + lc * 4;

    float4 wa0 = *(const float4*)wp;
    float4 wa1 = *(const float4*)(wp + 8 * UU);
    float4 xb0 = *(const float4*)xp;
    float4 xb1 = *(const float4*)(xp + 8 * TT);

    unsigned long long acc[8][4];
#pragma unroll
    for (int i = 0; i < 8; i++)
#pragma unroll
        for (int j = 0; j < 4; j++) acc[i][j] = 0ull;

    const unsigned bs_base = (unsigned)__cvta_generic_to_shared(&Bs[0][0]);
    const int g0 = tx * 2, g1 = tx * 2 + 1;
    const unsigned off0 = ((unsigned)(g0 ^ (g0 >> 3))) << 4;  // swizzled byte offset
    const unsigned off1 = ((unsigned)(g1 ^ (g1 >> 3))) << 4;

#pragma unroll 1
    for (int ch = 0; ch < FF / TK; ch++) {
        __syncthreads();
        *(float4*)(&As[lk][lc * 4])     = wa0;
        *(float4*)(&As[lk + 8][lc * 4]) = wa1;
        *(float4*)((char*)Bs + lk * (TN * 4) + pc * 16)       = xb0;
        *(float4*)((char*)Bs + (lk + 8) * (TN * 4) + pc * 16) = xb1;
        __syncthreads();

        if (ch + 1 < FF / TK) {          // prefetch next stage into registers
            wp += (size_t)TK * UU;
            xp += (size_t)TK * TT;
            wa0 = *(const float4*)wp;
            wa1 = *(const float4*)(wp + 8 * UU);
            xb0 = *(const float4*)xp;
            xb1 = *(const float4*)(xp + 8 * TT);
        }

#pragma unroll
        for (int k = 0; k < TK; k++) {
            unsigned long long b0, b1, b2v, b3v;
            const unsigned baddr = bs_base + (unsigned)(k * (TN * 4));
            lds_v2(b0, b1, baddr + off0);   // t cols 0..3 of micro-tile
            lds_v2(b2v, b3v, baddr + off1); // t cols 4..7
            const float4 av0 = *(const float4*)(&As[k][ty8]);
            const float4 av1 = *(const float4*)(&As[k][ty8 + 4]);
            const float av[8] = {av0.x, av0.y, av0.z, av0.w,
                                 av1.x, av1.y, av1.z, av1.w};
#pragma unroll
            for (int i = 0; i < 8; i++) {
                const unsigned long long a = splat2(av[i]);
                fma2(acc[i][0], a, b0);
                fma2(acc[i][1], a, b1);
                fma2(acc[i][2], a, b2v);
                fma2(acc[i][3], a, b3v);
            }
        }
    }

    // ---- epilogue: threshold + store [B, U, T] ----
    float* op = out + ((size_t)bz * UU + (u0 + ty8)) * TT + (t0 + tx * 8);
#pragma unroll
    for (int i = 0; i < 8; i++) {
        const float2 p0 = unpack2(acc[i][0]);
        const float2 p1 = unpack2(acc[i][1]);
        const float2 p2 = unpack2(acc[i][2]);
        const float2 p3 = unpack2(acc[i][3]);
        const float4 o0 = make_float4(p0.x > 1.0f ? 1.0f : 0.0f,
                                      p0.y > 1.0f ? 1.0f : 0.0f,
                                      p1.x > 1.0f ? 1.0f : 0.0f,
                                      p1.y > 1.0f ? 1.0f : 0.0f);
        const float4 o1 = make_float4(p2.x > 1.0f ? 1.0f : 0.0f,
                                      p2.y > 1.0f ? 1.0f : 0.0f,
                                      p3.x > 1.0f ? 1.0f : 0.0f,
                                      p3.y > 1.0f ? 1.0f : 0.0f);
        *(float4*)(op + (size_t)i * TT)     = o0;
        *(float4*)(op + (size_t)i * TT + 4) = o1;
    }
}

extern "C" void kernel_launch(void* const* d_in, const int* in_sizes, int n_in,
                              void* d_out, int out_size) {
    const float* x = (const float*)d_in[0];   // inputs [B, F, T]
    const float* w = (const float*)d_in[1];   // w      [F, U]
    // defensive: tolerate swapped metadata order
    if (n_in >= 2 && in_sizes[0] == FF * UU && in_sizes[1] == BB * FF * TT) {
        const float* t = x; x = w; w = t;
    }
    float* out = (float*)d_out;               // [B, U, T]

    dim3 grid(TT / TN, UU / TM, BB);          // (2, 8, 128)
    snn_gemm_kernel<<<grid, NTHREADS>>>(x, w, out);
}

// round 4
// speedup vs baseline: 1.0246x; 1.0246x over previous
#include <cuda_runtime.h>
#include <cstdint>
#include <cstddef>

// ---------------- problem constants ----------------
#define BB 128
#define FF 512
#define TT 256
#define UU 1024

// ---------------- GEMM tiling ----------------
#define CTA_M 128
#define CTA_N 256
#define KC    32            // k per chunk (4 ksteps of 8)
#define NCHUNK (FF / KC)    // 16
#define NTHREADS 256        // 8 warps, 2(M) x 4(N), warp tile 64x64

#define FLAG_DELTA 1e-4f
#define FLAG_CAP   (1u << 22)   // 4M entries

// ---------------- scratch (device globals) ----------------
__device__ float g_a_hi[(size_t)64 * 64 * 32 * 4];
__device__ float g_a_lo[(size_t)64 * 64 * 32 * 4];
__device__ float g_b_hi[(size_t)BB * 32 * 32 * 32 * 4];
__device__ float g_b_lo[(size_t)BB * 32 * 32 * 32 * 4];
__device__ unsigned int g_flag_count;
__device__ unsigned int g_flag_list[FLAG_CAP];   // packed: b[18:25) | u[8:18) | t[0:8)

// ---------------- helpers ----------------
__device__ __forceinline__ float tf32_rne(float a) {
    unsigned u = __float_as_uint(a);
    unsigned r = (u + 0xFFFu + ((u >> 13) & 1u)) & 0xFFFFE000u;  // RNE to tf32
    return __uint_as_float(r);
}

__device__ __forceinline__ void cp16(uint32_t dst, const void* src) {
    asm volatile("cp.async.cg.shared.global [%0], [%1], 16;" :: "r"(dst), "l"(src));
}
__device__ __forceinline__ void cp_commit() { asm volatile("cp.async.commit_group;"); }
__device__ __forceinline__ void cp_wait1() { asm volatile("cp.async.wait_group 1;"); }
__device__ __forceinline__ void cp_wait0() { asm volatile("cp.async.wait_group 0;"); }

__device__ __forceinline__ void mma_tf32(float* c, const float4& a, const float2& b) {
    asm volatile(
        "mma.sync.aligned.m16n8k8.row.col.f32.tf32.tf32.f32 "
        "{%0,%1,%2,%3}, {%4,%5,%6,%7}, {%8,%9}, {%0,%1,%2,%3};"
        : "+f"(c[0]), "+f"(c[1]), "+f"(c[2]), "+f"(c[3])
        : "r"(__float_as_uint(a.x)), "r"(__float_as_uint(a.y)),
          "r"(__float_as_uint(a.z)), "r"(__float_as_uint(a.w)),
          "r"(__float_as_uint(b.x)), "r"(__float_as_uint(b.y)));
}

// ---------------- pre-pass: split + fragment-permute ----------------
__global__ __launch_bounds__(256)
void prep_w_kernel(const float* __restrict__ w) {
    const int idx = blockIdx.x * 256 + threadIdx.x;     // < 131072
    const int lane = idx & 31;
    const int mc   = (idx >> 5) & 63;
    const int kc   = idx >> 11;
    const int m = mc * 16 + (lane >> 2);
    const int k = kc * 8 + (lane & 3);
    const float v0 = w[(size_t)k * UU + m];
    const float v1 = w[(size_t)k * UU + m + 8];
    const float v2 = w[(size_t)(k + 4) * UU + m];
    const float v3 = w[(size_t)(k + 4) * UU + m + 8];
    float4 hi, lo;
    hi.x = tf32_rne(v0); lo.x = tf32_rne(v0 - hi.x);
    hi.y = tf32_rne(v1); lo.y = tf32_rne(v1 - hi.y);
    hi.z = tf32_rne(v2); lo.z = tf32_rne(v2 - hi.z);
    hi.w = tf32_rne(v3); lo.w = tf32_rne(v3 - hi.w);
    ((float4*)g_a_hi)[idx] = hi;
    ((float4*)g_a_lo)[idx] = lo;
    if (idx == 0) g_flag_count = 0;     // reset fixup counter each call
}

__global__ __launch_bounds__(256)
void prep_x_kernel(const float* __restrict__ x) {
    const int idx = blockIdx.x * 256 + threadIdx.x;     // < 4194304
    const int lane = idx & 31;
    const int nc   = (idx >> 5) & 31;
    const int kp   = (idx >> 10) & 31;
    const int b    = idx >> 15;
    const int n = nc * 8 + (lane >> 2);
    const int k = kp * 16 + (lane & 3);
    const float* xp = x + ((size_t)b * FF + k) * TT + n;
    const float v0 = xp[0];
    const float v1 = xp[4 * TT];
    const float v2 = xp[8 * TT];
    const float v3 = xp[12 * TT];
    float4 hi, lo;
    hi.x = tf32_rne(v0); lo.x = tf32_rne(v0 - hi.x);
    hi.y = tf32_rne(v1); lo.y = tf32_rne(v1 - hi.y);
    hi.z = tf32_rne(v2); lo.z = tf32_rne(v2 - hi.z);
    hi.w = tf32_rne(v3); lo.w = tf32_rne(v3 - hi.w);
    ((float4*)g_b_hi)[idx] = hi;
    ((float4*)g_b_lo)[idx] = lo;
}

// ---------------- GEMM kernel ----------------
#define A_BYTES 16384
#define B_BYTES 32768
#define A_HI_OFF 0
#define A_LO_OFF 16384
#define B_HI_OFF 32768
#define B_LO_OFF 65536
#define STAGE_BYTES 98304
#define SMEM_TOTAL (2 * STAGE_BYTES)   // 192 KB

__global__ __launch_bounds__(NTHREADS, 1)
void snn_mma_gemm(float* __restrict__ out) {
    extern __shared__ __align__(128) char smem[];
    const uint32_t sb = (uint32_t)__cvta_generic_to_shared(smem);

    const int tid  = threadIdx.x;
    const int lane = tid & 31;
    const int wid  = tid >> 5;
    const int wm   = wid & 1;
    const int wn   = wid >> 1;
    const int mc0  = blockIdx.x * 8;
    const int b    = blockIdx.y;

    auto issue = [&](int c, int s) {
        const uint32_t st = sb + s * STAGE_BYTES;
#pragma unroll
        for (int j = 0; j < 4; j++) {
            const int o = tid + j * 256;
            const int kt = o >> 8;
            const int off = o & 255;
            const size_t srcf = ((size_t)(c * 4 + kt) * 64 + mc0) * 128 + (size_t)off * 4;
            cp16(st + A_HI_OFF + o * 16, g_a_hi + srcf);
            cp16(st + A_LO_OFF + o * 16, g_a_lo + srcf);
        }
#pragma unroll
        for (int j = 0; j < 8; j++) {
            const int o = tid + j * 256;
            const int kp = o >> 10;
            const int off = o & 1023;
            const size_t srcf = ((size_t)(b * 32 + c * 2 + kp)) * 4096 + (size_t)off * 4;
            cp16(st + B_HI_OFF + o * 16, g_b_hi + srcf);
            cp16(st + B_LO_OFF + o * 16, g_b_lo + srcf);
        }
        cp_commit();
    };

    float acc[4][8][4];
#pragma unroll
    for (int mt = 0; mt < 4; mt++)
#pragma unroll
        for (int nt = 0; nt < 8; nt++)
#pragma unroll
            for (int q = 0; q < 4; q++) acc[mt][nt][q] = 0.0f;

    issue(0, 0);
    issue(1, 1);

#pragma unroll 1
    for (int c = 0; c < NCHUNK; c++) {
        if (c == NCHUNK - 1) cp_wait0(); else cp_wait1();
        __syncthreads();

        const int s = c & 1;
        const float4* As_hi = (const float4*)(smem + s * STAGE_BYTES + A_HI_OFF);
        const float4* As_lo = (const float4*)(smem + s * STAGE_BYTES + A_LO_OFF);
        const float2* Bs_hi = (const float2*)(smem + s * STAGE_BYTES + B_HI_OFF);
        const float2* Bs_lo = (const float2*)(smem + s * STAGE_BYTES + B_LO_OFF);

#pragma unroll
        for (int kt = 0; kt < 4; kt++) {
            const int kp = kt >> 1, kh = kt & 1;
            float4 fa_hi[4], fa_lo[4];
            float2 fb_hi[8], fb_lo[8];
#pragma unroll
            for (int mt = 0; mt < 4; mt++) {
                const int ai = (kt * 8 + wm * 4 + mt) * 32 + lane;
                fa_hi[mt] = As_hi[ai];
                fa_lo[mt] = As_lo[ai];
            }
#pragma unroll
            for (int nt = 0; nt < 8; nt++) {
                const int bi = ((kp * 32 + wn * 8 + nt) * 32 + lane) * 2 + kh;
                fb_hi[nt] = Bs_hi[bi];
                fb_lo[nt] = Bs_lo[bi];
            }
#pragma unroll
            for (int mt = 0; mt < 4; mt++)
#pragma unroll
                for (int nt = 0; nt < 8; nt++)
                    mma_tf32(acc[mt][nt], fa_hi[mt], fb_hi[nt]);
#pragma unroll
            for (int mt = 0; mt < 4; mt++)
#pragma unroll
                for (int nt = 0; nt < 8; nt++)
                    mma_tf32(acc[mt][nt], fa_hi[mt], fb_lo[nt]);
#pragma unroll
            for (int mt = 0; mt < 4; mt++)
#pragma unroll
                for (int nt = 0; nt < 8; nt++)
                    mma_tf32(acc[mt][nt], fa_lo[mt], fb_hi[nt]);
        }

        __syncthreads();
        if (c + 2 < NCHUNK) issue(c + 2, s);
    }

    // ---- epilogue: threshold + flag near-threshold + store ----
    const int m_base = mc0 * 16 + wm * 64 + (lane >> 2);
    const int t_base = wn * 64 + (lane & 3) * 2;
#pragma unroll
    for (int mt = 0; mt < 4; mt++) {
#pragma unroll
        for (int nt = 0; nt < 8; nt++) {
            const int m = m_base + mt * 16;
            const int t = t_base + nt * 8;
#pragma unroll
            for (int h = 0; h < 2; h++) {     // h=0 -> row m, h=1 -> row m+8
                const int mm = m + h * 8;
                const float v0 = acc[mt][nt][h * 2 + 0];
                const float v1 = acc[mt][nt][h * 2 + 1];
                float2 r;
                r.x = v0 > 1.0f ? 1.0f : 0.0f;
                r.y = v1 > 1.0f ? 1.0f : 0.0f;
                *(float2*)(out + ((size_t)b * UU + mm) * TT + t) = r;
                if (fabsf(v0 - 1.0f) < FLAG_DELTA) {
                    unsigned idx = atomicAdd(&g_flag_count, 1u);
                    if (idx < FLAG_CAP)
                        g_flag_list[idx] = ((unsigned)b << 18) | ((unsigned)mm << 8) | (unsigned)t;
                }
                if (fabsf(v1 - 1.0f) < FLAG_DELTA) {
                    unsigned idx = atomicAdd(&g_flag_count, 1u);
                    if (idx < FLAG_CAP)
                        g_flag_list[idx] = ((unsigned)b << 18) | ((unsigned)mm << 8) | (unsigned)(t + 1);
                }
            }
        }
    }
}

// ---------------- exact fixup: sequential-k fp32 chain (matches R1/reference) ----
__global__ __launch_bounds__(128)
void fixup_kernel(const float* __restrict__ x, const float* __restrict__ w,
                  float* __restrict__ out) {
    const unsigned n = min(g_flag_count, FLAG_CAP);
    const unsigned stride = gridDim.x * blockDim.x;
    for (unsigned i = blockIdx.x * blockDim.x + threadIdx.x; i < n; i += stride) {
        const unsigned code = g_flag_list[i];
        const int b = code >> 18;
        const int u = (code >> 8) & 1023;
        const int t = code & 255;
        const float* wp = w + u;                      // stride UU over f
        const float* xp = x + (size_t)b * FF * TT + t; // stride TT over f
        float acc = 0.0f;
#pragma unroll 8
        for (int f = 0; f < FF; f++)
            acc = __fmaf_rn(wp[(size_t)f * UU], xp[(size_t)f * TT], acc);
        out[((size_t)b * UU + u) * TT + t] = acc > 1.0f ? 1.0f : 0.0f;
    }
}

// ---------------- host side ----------------
extern "C" void kernel_launch(void* const* d_in, const int* in_sizes, int n_in,
                              void* d_out, int out_size) {
    const float* x = (const float*)d_in[0];   // [B, F, T]
    const float* w = (const float*)d_in[1];   // [F, U]
    if (n_in >= 2 && in_sizes[0] == FF * UU && in_sizes[1] == BB * FF * TT) {
        const float* t = x; x = w; w = t;
    }
    float* out = (float*)d_out;

    prep_w_kernel<<<131072 / 256, 256>>>(w);
    prep_x_kernel<<<4194304 / 256, 256>>>(x);

    cudaFuncSetAttribute(snn_mma_gemm, cudaFuncAttributeMaxDynamicSharedMemorySize,
                         SMEM_TOTAL);
    snn_mma_gemm<<<dim3(UU / CTA_M, BB), NTHREADS, SMEM_TOTAL>>>(out);

    fixup_kernel<<<256, 128>>>(x, w, out);
}

// round 5
// speedup vs baseline: 1.0336x; 1.0088x over previous
#include <cuda_runtime.h>
#include <cstdint>
#include <cstddef>

// ---------------- problem constants ----------------
#define BB 128
#define FF 512
#define TT 256
#define UU 1024

// ---------------- GEMM tiling ----------------
#define CTA_M 128
#define CTA_N 256
#define KC    32            // k per chunk (4 ksteps of 8)
#define NCHUNK (FF / KC)    // 16
#define NTHREADS 256        // 8 warps, 2(M) x 4(N), warp tile 64x64

#define FLAG_DELTA 1e-4f
#define FLAG_CAP   (1u << 20)

// ---------------- scratch (device globals) ----------------
// A = W^T fragment-permuted tf32 hi/lo: A_perm[kc(64)][mc(64)][lane(32)][4]
__device__ float g_a_hi[(size_t)64 * 64 * 32 * 4];
__device__ float g_a_lo[(size_t)64 * 64 * 32 * 4];
__device__ unsigned int g_flag_count;
__device__ unsigned int g_flag_list[FLAG_CAP];   // b[18:25) | u[8:18) | t[0:8)

// ---------------- helpers ----------------
__device__ __forceinline__ float tf32_rne(float a) {
    unsigned u = __float_as_uint(a);
    unsigned r = (u + 0xFFFu + ((u >> 13) & 1u)) & 0xFFFFE000u;
    return __uint_as_float(r);
}

__device__ __forceinline__ void cp16(uint32_t dst, const void* src) {
    asm volatile("cp.async.cg.shared.global [%0], [%1], 16;" :: "r"(dst), "l"(src));
}
__device__ __forceinline__ void cp_commit() { asm volatile("cp.async.commit_group;"); }
__device__ __forceinline__ void cp_wait1() { asm volatile("cp.async.wait_group 1;"); }
__device__ __forceinline__ void cp_wait0() { asm volatile("cp.async.wait_group 0;"); }

__device__ __forceinline__ void mma_tf32(float* c, const float4& a, const float2& b) {
    asm volatile(
        "mma.sync.aligned.m16n8k8.row.col.f32.tf32.tf32.f32 "
        "{%0,%1,%2,%3}, {%4,%5,%6,%7}, {%8,%9}, {%0,%1,%2,%3};"
        : "+f"(c[0]), "+f"(c[1]), "+f"(c[2]), "+f"(c[3])
        : "r"(__float_as_uint(a.x)), "r"(__float_as_uint(a.y)),
          "r"(__float_as_uint(a.z)), "r"(__float_as_uint(a.w)),
          "r"(__float_as_uint(b.x)), "r"(__float_as_uint(b.y)));
}

// ---------------- pre-pass: split + fragment-permute W only ----------------
__global__ __launch_bounds__(256)
void prep_w_kernel(const float* __restrict__ w) {
    const int idx = blockIdx.x * 256 + threadIdx.x;     // < 131072
    const int lane = idx & 31;
    const int mc   = (idx >> 5) & 63;
    const int kc   = idx >> 11;
    const int m = mc * 16 + (lane >> 2);
    const int k = kc * 8 + (lane & 3);
    const float v0 = w[(size_t)k * UU + m];
    const float v1 = w[(size_t)k * UU + m + 8];
    const float v2 = w[(size_t)(k + 4) * UU + m];
    const float v3 = w[(size_t)(k + 4) * UU + m + 8];
    float4 hi, lo;
    hi.x = tf32_rne(v0); lo.x = v0 - hi.x;
    hi.y = tf32_rne(v1); lo.y = v1 - hi.y;
    hi.z = tf32_rne(v2); lo.z = v2 - hi.z;
    hi.w = tf32_rne(v3); lo.w = v3 - hi.w;
    ((float4*)g_a_hi)[idx] = hi;
    ((float4*)g_a_lo)[idx] = lo;
    if (idx == 0) g_flag_count = 0;
}

// ---------------- GEMM: smem layout ----------------
// A stages:   2 x (hi 16KB + lo 16KB)            = 65536
// raw X:      2 x 32 rows x 1040B (16B row pad)  = 66560
// Bs split:   hi 32KB + lo 32KB (single buffer)  = 65536
#define A_OFF      0
#define A_STAGE    32768
#define A_LO       16384
#define RAW_OFF    65536
#define RAW_STAGE  33280
#define RAW_ROWF   260              // floats per padded row
#define BS_OFF     132096
#define BS_LO      32768
#define SMEM_TOTAL 197632

__global__ __launch_bounds__(NTHREADS, 1)
void snn_mma_gemm(const float* __restrict__ x, float* __restrict__ out) {
    extern __shared__ __align__(1024) char smem[];
    const uint32_t sb = (uint32_t)__cvta_generic_to_shared(smem);

    const int tid  = threadIdx.x;
    const int lane = tid & 31;
    const int wid  = tid >> 5;
    const int wm   = wid & 1;
    const int wn   = wid >> 1;
    const int mc0  = blockIdx.x * 8;
    const int b    = blockIdx.y;

    const float* xb = x + (size_t)b * FF * TT;

    auto issue = [&](int c, int s) {
        // A hi/lo (fragment-permuted in global)
        const uint32_t ast = sb + A_OFF + s * A_STAGE;
#pragma unroll
        for (int j = 0; j < 4; j++) {
            const int o = tid + j * 256;
            const int kt = o >> 8;
            const int off = o & 255;
            const size_t srcf = ((size_t)(c * 4 + kt) * 64 + mc0) * 128 + (size_t)off * 4;
            cp16(ast + o * 16, g_a_hi + srcf);
            cp16(ast + A_LO + o * 16, g_a_lo + srcf);
        }
        // raw X tile: 32 rows x 1KB, padded rows
        const uint32_t rst = sb + RAW_OFF + s * RAW_STAGE;
#pragma unroll
        for (int j = 0; j < 8; j++) {
            const int o = tid + j * 256;
            const int row = o >> 6;
            const int col = o & 63;
            cp16(rst + row * 1040 + col * 16,
                 xb + ((size_t)(c * KC + row)) * TT + col * 4);
        }
        cp_commit();
    };

    float acc[4][8][4];
#pragma unroll
    for (int mt = 0; mt < 4; mt++)
#pragma unroll
        for (int nt = 0; nt < 8; nt++)
#pragma unroll
            for (int q = 0; q < 4; q++) acc[mt][nt][q] = 0.0f;

    issue(0, 0);
    issue(1, 1);

    float2* bs_hi = (float2*)(smem + BS_OFF);
    float2* bs_lo = (float2*)(smem + BS_OFF + BS_LO);

#pragma unroll 1
    for (int c = 0; c < NCHUNK; c++) {
        if (c == NCHUNK - 1) cp_wait0(); else cp_wait1();
        __syncthreads();                         // raw[s]/A[s] visible

        const int s = c & 1;
        const float* raw = (const float*)(smem + RAW_OFF + s * RAW_STAGE);

        // ---- in-kernel split: raw fp32 -> tf32 hi/lo fragments ----
        // fragment layout: float2 at ((kp*2+kh)*32 + nc)*32 + lane
#pragma unroll
        for (int j = 0; j < 8; j++) {
            const int slot = tid + j * 256;      // < 2048
            const int ls = slot & 31;
            const int nc = (slot >> 5) & 31;
            const int kp = slot >> 10;
            const int n  = nc * 8 + (ls >> 2);
            const int k0 = kp * 16 + (ls & 3);
            const float v0 = raw[(k0     ) * RAW_ROWF + n];
            const float v1 = raw[(k0 +  4) * RAW_ROWF + n];
            const float v2 = raw[(k0 +  8) * RAW_ROWF + n];
            const float v3 = raw[(k0 + 12) * RAW_ROWF + n];
            float2 hE, hO, lE, lO;
            hE.x = tf32_rne(v0); lE.x = v0 - hE.x;
            hE.y = tf32_rne(v1); lE.y = v1 - hE.y;
            hO.x = tf32_rne(v2); lO.x = v2 - hO.x;
            hO.y = tf32_rne(v3); lO.y = v3 - hO.y;
            const int fiE = ((kp * 2 + 0) * 32 + nc) * 32 + ls;
            const int fiO = ((kp * 2 + 1) * 32 + nc) * 32 + ls;
            bs_hi[fiE] = hE; bs_lo[fiE] = lE;
            bs_hi[fiO] = hO; bs_lo[fiO] = lO;
        }
        __syncthreads();                         // Bs ready

        const float4* As_hi = (const float4*)(smem + A_OFF + s * A_STAGE);
        const float4* As_lo = (const float4*)(smem + A_OFF + s * A_STAGE + A_LO);

#pragma unroll
        for (int kt = 0; kt < 4; kt++) {
            const int kp = kt >> 1, kh = kt & 1;
            float4 fa_hi[4], fa_lo[4];
            float2 fb_hi[8], fb_lo[8];
#pragma unroll
            for (int mt = 0; mt < 4; mt++) {
                const int ai = (kt * 8 + wm * 4 + mt) * 32 + lane;
                fa_hi[mt] = As_hi[ai];
                fa_lo[mt] = As_lo[ai];
            }
#pragma unroll
            for (int nt = 0; nt < 8; nt++) {
                const int bi = ((kp * 2 + kh) * 32 + wn * 8 + nt) * 32 + lane;
                fb_hi[nt] = bs_hi[bi];
                fb_lo[nt] = bs_lo[bi];
            }
#pragma unroll
            for (int mt = 0; mt < 4; mt++)
#pragma unroll
                for (int nt = 0; nt < 8; nt++)
                    mma_tf32(acc[mt][nt], fa_hi[mt], fb_hi[nt]);
#pragma unroll
            for (int mt = 0; mt < 4; mt++)
#pragma unroll
                for (int nt = 0; nt < 8; nt++)
                    mma_tf32(acc[mt][nt], fa_hi[mt], fb_lo[nt]);
#pragma unroll
            for (int mt = 0; mt < 4; mt++)
#pragma unroll
                for (int nt = 0; nt < 8; nt++)
                    mma_tf32(acc[mt][nt], fa_lo[mt], fb_hi[nt]);
        }

        __syncthreads();                         // reads of A[s], raw[s], Bs done
        if (c + 2 < NCHUNK) issue(c + 2, s);
    }

    // ---- epilogue: threshold + flag near-threshold + store ----
    const int m_base = mc0 * 16 + wm * 64 + (lane >> 2);
    const int t_base = wn * 64 + (lane & 3) * 2;
#pragma unroll
    for (int mt = 0; mt < 4; mt++) {
#pragma unroll
        for (int nt = 0; nt < 8; nt++) {
            const int m = m_base + mt * 16;
            const int t = t_base + nt * 8;
#pragma unroll
            for (int h = 0; h < 2; h++) {
                const int mm = m + h * 8;
                const float v0 = acc[mt][nt][h * 2 + 0];
                const float v1 = acc[mt][nt][h * 2 + 1];
                float2 r;
                r.x = v0 > 1.0f ? 1.0f : 0.0f;
                r.y = v1 > 1.0f ? 1.0f : 0.0f;
                *(float2*)(out + ((size_t)b * UU + mm) * TT + t) = r;
                if (fabsf(v0 - 1.0f) < FLAG_DELTA) {
                    unsigned idx = atomicAdd(&g_flag_count, 1u);
                    if (idx < FLAG_CAP)
                        g_flag_list[idx] = ((unsigned)b << 18) | ((unsigned)mm << 8) | (unsigned)t;
                }
                if (fabsf(v1 - 1.0f) < FLAG_DELTA) {
                    unsigned idx = atomicAdd(&g_flag_count, 1u);
                    if (idx < FLAG_CAP)
                        g_flag_list[idx] = ((unsigned)b << 18) | ((unsigned)mm << 8) | (unsigned)(t + 1);
                }
            }
        }
    }
}

// ---------------- exact fixup: warp-cooperative gather + sequential fp32 chain ----
#define FIX_WARPS 4
__global__ __launch_bounds__(FIX_WARPS * 32)
void fixup_kernel(const float* __restrict__ x, const float* __restrict__ w,
                  float* __restrict__ out) {
    __shared__ float ws[FIX_WARPS][FF];
    __shared__ float xs[FIX_WARPS][FF];
    const unsigned n = min(g_flag_count, (unsigned)FLAG_CAP);
    const int lane = threadIdx.x & 31;
    const int wrp  = threadIdx.x >> 5;
    const unsigned gw = blockIdx.x * FIX_WARPS + wrp;
    const unsigned nw = gridDim.x * FIX_WARPS;
    for (unsigned i = gw; i < n; i += nw) {
        const unsigned code = g_flag_list[i];
        const int b = code >> 18;
        const int u = (code >> 8) & 1023;
        const int t = code & 255;
        const float* wp = w + u;
        const float* xp = x + (size_t)b * FF * TT + t;
#pragma unroll
        for (int j = 0; j < FF / 32; j++) {      // MLP-32 parallel gather
            const int f = lane + j * 32;
            ws[wrp][f] = wp[(size_t)f * UU];
            xs[wrp][f] = xp[(size_t)f * TT];
        }
        __syncwarp();
        if (lane == 0) {
            float acc = 0.0f;                    // exact sequential-k fp32 chain
#pragma unroll 16
            for (int f = 0; f < FF; f++)
                acc = __fmaf_rn(ws[wrp][f], xs[wrp][f], acc);
            out[((size_t)b * UU + u) * TT + t] = acc > 1.0f ? 1.0f : 0.0f;
        }
        __syncwarp();
    }
}

// ---------------- host side ----------------
extern "C" void kernel_launch(void* const* d_in, const int* in_sizes, int n_in,
                              void* d_out, int out_size) {
    const float* x = (const float*)d_in[0];   // [B, F, T]
    const float* w = (const float*)d_in[1];   // [F, U]
    if (n_in >= 2 && in_sizes[0] == FF * UU && in_sizes[1] == BB * FF * TT) {
        const float* t = x; x = w; w = t;
    }
    float* out = (float*)d_out;

    prep_w_kernel<<<131072 / 256, 256>>>(w);

    cudaFuncSetAttribute(snn_mma_gemm, cudaFuncAttributeMaxDynamicSharedMemorySize,
                         SMEM_TOTAL);
    snn_mma_gemm<<<dim3(UU / CTA_M, BB), NTHREADS, SMEM_TOTAL>>>(x, out);

    fixup_kernel<<<512, FIX_WARPS * 32>>>(x, w, out);
}

// round 6
// speedup vs baseline: 1.1796x; 1.1412x over previous
#include <cuda_runtime.h>
#include <cstdint>
#include <cstddef>

// ---------------- problem constants ----------------
#define BB 128
#define FF 512
#define TT 256
#define UU 1024

// ---------------- GEMM tiling ----------------
#define CTA_M 128
#define CTA_N 256
#define KC    32            // k per chunk (4 ksteps of 8)
#define NCHUNK (FF / KC)    // 16
#define NTHREADS 256        // 8 warps: 2(M) x 4(N), warp tile 64x64

#define FLAG_DELTA 4e-3f    // tier-1 band (~10 sigma of single-pass tf32 error)
#define EXACT_BAND 5e-5     // tier-2 band (fp64 vs fp32-seq ambiguity)
#define FLAG_CAP   (1u << 20)

// ---------------- scratch (device globals) ----------------
__device__ float g_a_perm[(size_t)64 * 64 * 32 * 4];   // W fragment-permuted fp32
__device__ float g_wt[(size_t)UU * FF];                // W^T  [U][F]
__device__ float g_xt[(size_t)BB * TT * FF];           // X^T  [B][T][F]
__device__ unsigned int g_flag_count;
__device__ unsigned int g_flag_list[FLAG_CAP];         // b[18:25)|u[8:18)|t[0:8)

// ---------------- helpers ----------------
__device__ __forceinline__ void cp16(uint32_t dst, const void* src) {
    asm volatile("cp.async.cg.shared.global [%0], [%1], 16;" :: "r"(dst), "l"(src));
}
__device__ __forceinline__ void cp_commit() { asm volatile("cp.async.commit_group;"); }
__device__ __forceinline__ void cp_wait1() { asm volatile("cp.async.wait_group 1;"); }
__device__ __forceinline__ void cp_wait0() { asm volatile("cp.async.wait_group 0;"); }

__device__ __forceinline__ void mma_tf32(float* c, const float4& a, const float2& b) {
    asm volatile(
        "mma.sync.aligned.m16n8k8.row.col.f32.tf32.tf32.f32 "
        "{%0,%1,%2,%3}, {%4,%5,%6,%7}, {%8,%9}, {%0,%1,%2,%3};"
        : "+f"(c[0]), "+f"(c[1]), "+f"(c[2]), "+f"(c[3])
        : "r"(__float_as_uint(a.x)), "r"(__float_as_uint(a.y)),
          "r"(__float_as_uint(a.z)), "r"(__float_as_uint(a.w)),
          "r"(__float_as_uint(b.x)), "r"(__float_as_uint(b.y)));
}

// ---------------- pre-pass: fragment-permute W (fp32, no split) ----------------
__global__ __launch_bounds__(256)
void prep_w_kernel(const float* __restrict__ w) {
    const int idx = blockIdx.x * 256 + threadIdx.x;     // < 131072
    const int lane = idx & 31;
    const int mc   = (idx >> 5) & 63;
    const int kc   = idx >> 11;
    const int m = mc * 16 + (lane >> 2);
    const int k = kc * 8 + (lane & 3);
    float4 v;
    v.x = w[(size_t)k * UU + m];
    v.y = w[(size_t)k * UU + m + 8];
    v.z = w[(size_t)(k + 4) * UU + m];
    v.w = w[(size_t)(k + 4) * UU + m + 8];
    ((float4*)g_a_perm)[idx] = v;
    if (idx == 0) g_flag_count = 0;
}

// ---------------- transposes for coalesced fixup gathers ----------------
__global__ __launch_bounds__(256)
void transpose_w_kernel(const float* __restrict__ w) {  // [F][U] -> [U][F]
    __shared__ float tile[32][33];
    const int u0 = blockIdx.x * 32, f0 = blockIdx.y * 32;
    const int tx = threadIdx.x, ty = threadIdx.y;       // 32 x 8
#pragma unroll
    for (int r = 0; r < 32; r += 8)
        tile[ty + r][tx] = w[(size_t)(f0 + ty + r) * UU + u0 + tx];
    __syncthreads();
#pragma unroll
    for (int r = 0; r < 32; r += 8)
        g_wt[(size_t)(u0 + ty + r) * FF + f0 + tx] = tile[tx][ty + r];
}

__global__ __launch_bounds__(256)
void transpose_x_kernel(const float* __restrict__ x) {  // [B][F][T] -> [B][T][F]
    __shared__ float tile[32][33];
    const int b  = blockIdx.z;
    const int t0 = blockIdx.x * 32, f0 = blockIdx.y * 32;
    const int tx = threadIdx.x, ty = threadIdx.y;
    const float* xp = x + ((size_t)b * FF + f0) * TT + t0;
#pragma unroll
    for (int r = 0; r < 32; r += 8)
        tile[ty + r][tx] = xp[(size_t)(ty + r) * TT + tx];
    __syncthreads();
    float* op = g_xt + ((size_t)b * TT + t0) * FF + f0;
#pragma unroll
    for (int r = 0; r < 32; r += 8)
        op[(size_t)(ty + r) * FF + tx] = tile[tx][ty + r];
}

// ---------------- GEMM: single-pass tf32, fragments straight from raw X ----
// smem: A 2 x 16KB | raw X 2 x 33280 (260-float padded rows)
#define A_OFF      0
#define A_STAGE    16384
#define RAW_OFF    32768
#define RAW_STAGE  33280
#define RAW_ROWF   260
#define SMEM_TOTAL 99328

__global__ __launch_bounds__(NTHREADS, 1)
void snn_mma_gemm(const float* __restrict__ x, float* __restrict__ out) {
    extern __shared__ __align__(1024) char smem[];
    const uint32_t sb = (uint32_t)__cvta_generic_to_shared(smem);

    const int tid  = threadIdx.x;
    const int lane = tid & 31;
    const int wid  = tid >> 5;
    const int wm   = wid & 1;
    const int wn   = wid >> 1;
    const int mc0  = blockIdx.x * 8;
    const int b    = blockIdx.y;

    const float* xb = x + (size_t)b * FF * TT;

    auto issue = [&](int c, int s) {
        const uint32_t ast = sb + A_OFF + s * A_STAGE;   // A fragments: 1024 x 16B
#pragma unroll
        for (int j = 0; j < 4; j++) {
            const int o = tid + j * 256;
            const int kt = o >> 8;
            const int off = o & 255;
            const size_t srcf = ((size_t)(c * 4 + kt) * 64 + mc0) * 128 + (size_t)off * 4;
            cp16(ast + o * 16, g_a_perm + srcf);
        }
        const uint32_t rst = sb + RAW_OFF + s * RAW_STAGE;  // raw X: 32 rows x 1KB
#pragma unroll
        for (int j = 0; j < 8; j++) {
            const int o = tid + j * 256;
            const int row = o >> 6;
            const int col = o & 63;
            cp16(rst + row * 1040 + col * 16,
                 xb + ((size_t)(c * KC + row)) * TT + col * 4);
        }
        cp_commit();
    };

    float acc[4][8][4];
#pragma unroll
    for (int mt = 0; mt < 4; mt++)
#pragma unroll
        for (int nt = 0; nt < 8; nt++)
#pragma unroll
            for (int q = 0; q < 4; q++) acc[mt][nt][q] = 0.0f;

    issue(0, 0);
    issue(1, 1);

#pragma unroll 1
    for (int c = 0; c < NCHUNK; c++) {
        if (c == NCHUNK - 1) cp_wait0(); else cp_wait1();
        __syncthreads();

        const int s = c & 1;
        const float*  raw = (const float*)(smem + RAW_OFF + s * RAW_STAGE);
        const float4* As  = (const float4*)(smem + A_OFF + s * A_STAGE);

#pragma unroll
        for (int kt = 0; kt < 4; kt++) {
            float4 fa[4];
            float2 fb[8];
#pragma unroll
            for (int mt = 0; mt < 4; mt++)
                fa[mt] = As[(kt * 8 + wm * 4 + mt) * 32 + lane];
            const int kb = kt * 8 + (lane & 3);
            const int nb = (lane >> 2);
#pragma unroll
            for (int nt = 0; nt < 8; nt++) {
                const int n = (wn * 8 + nt) * 8 + nb;
                fb[nt].x = raw[kb * RAW_ROWF + n];        // HW truncates to tf32
                fb[nt].y = raw[(kb + 4) * RAW_ROWF + n];
            }
#pragma unroll
            for (int mt = 0; mt < 4; mt++)
#pragma unroll
                for (int nt = 0; nt < 8; nt++)
                    mma_tf32(acc[mt][nt], fa[mt], fb[nt]);
        }

        __syncthreads();
        if (c + 2 < NCHUNK) issue(c + 2, s);
    }

    // ---- epilogue: threshold + flag near-threshold + store ----
    const int m_base = mc0 * 16 + wm * 64 + (lane >> 2);
    const int t_base = wn * 64 + (lane & 3) * 2;
#pragma unroll
    for (int mt = 0; mt < 4; mt++) {
#pragma unroll
        for (int nt = 0; nt < 8; nt++) {
            const int m = m_base + mt * 16;
            const int t = t_base + nt * 8;
#pragma unroll
            for (int h = 0; h < 2; h++) {
                const int mm = m + h * 8;
                const float v0 = acc[mt][nt][h * 2 + 0];
                const float v1 = acc[mt][nt][h * 2 + 1];
                float2 r;
                r.x = v0 > 1.0f ? 1.0f : 0.0f;
                r.y = v1 > 1.0f ? 1.0f : 0.0f;
                *(float2*)(out + ((size_t)b * UU + mm) * TT + t) = r;
                if (fabsf(v0 - 1.0f) < FLAG_DELTA) {
                    unsigned idx = atomicAdd(&g_flag_count, 1u);
                    if (idx < FLAG_CAP)
                        g_flag_list[idx] = ((unsigned)b << 18) | ((unsigned)mm << 8) | (unsigned)t;
                }
                if (fabsf(v1 - 1.0f) < FLAG_DELTA) {
                    unsigned idx = atomicAdd(&g_flag_count, 1u);
                    if (idx < FLAG_CAP)
                        g_flag_list[idx] = ((unsigned)b << 18) | ((unsigned)mm << 8) | (unsigned)(t + 1);
                }
            }
        }
    }
}

// ---------------- two-tier fixup ----------------
// Tier 1: warp-per-element fp64 dot (coalesced from transposed arrays).
// Tier 2: |h64 - 1| < EXACT_BAND -> exact sequential fp32 chain (reference order).
#define FIX_WARPS 8
__global__ __launch_bounds__(FIX_WARPS * 32)
void fixup_kernel(float* __restrict__ out) {
    __shared__ float ws[FIX_WARPS][FF];
    __shared__ float xs[FIX_WARPS][FF];
    const unsigned n = min(g_flag_count, (unsigned)FLAG_CAP);
    const int lane = threadIdx.x & 31;
    const int wrp  = threadIdx.x >> 5;
    const unsigned gw = blockIdx.x * FIX_WARPS + wrp;
    const unsigned nw = gridDim.x * FIX_WARPS;
    for (unsigned i = gw; i < n; i += nw) {
        const unsigned code = g_flag_list[i];
        const int b = code >> 18;
        const int u = (code >> 8) & 1023;
        const int t = code & 255;
        const float4* wr = (const float4*)(g_wt + (size_t)u * FF);
        const float4* xr = (const float4*)(g_xt + ((size_t)b * TT + t) * FF);
        double s = 0.0;
        float4 wa[4], xa[4];
#pragma unroll
        for (int j = 0; j < 4; j++) {                 // coalesced: 512 floats each
            wa[j] = wr[lane + j * 32];
            xa[j] = xr[lane + j * 32];
            s += (double)wa[j].x * (double)xa[j].x;
            s += (double)wa[j].y * (double)xa[j].y;
            s += (double)wa[j].z * (double)xa[j].z;
            s += (double)wa[j].w * (double)xa[j].w;
        }
#pragma unroll
        for (int o = 16; o > 0; o >>= 1)              // deterministic tree-reduce
            s += __shfl_xor_sync(0xFFFFFFFFu, s, o);
        if (fabs(s - 1.0) > EXACT_BAND) {
            if (lane == 0)
                out[((size_t)b * UU + u) * TT + t] = (s > 1.0) ? 1.0f : 0.0f;
        } else {
            // rare: stage in f-order, replay exact sequential fp32 chain
#pragma unroll
            for (int j = 0; j < 4; j++) {
                const int f = 4 * (lane + j * 32);
                *(float4*)&ws[wrp][f] = wa[j];
                *(float4*)&xs[wrp][f] = xa[j];
            }
            __syncwarp();
            if (lane == 0) {
                float acc = 0.0f;
#pragma unroll 16
                for (int f = 0; f < FF; f++)
                    acc = __fmaf_rn(ws[wrp][f], xs[wrp][f], acc);
                out[((size_t)b * UU + u) * TT + t] = acc > 1.0f ? 1.0f : 0.0f;
            }
            __syncwarp();
        }
    }
}

// ---------------- host side ----------------
extern "C" void kernel_launch(void* const* d_in, const int* in_sizes, int n_in,
                              void* d_out, int out_size) {
    const float* x = (const float*)d_in[0];   // [B, F, T]
    const float* w = (const float*)d_in[1];   // [F, U]
    if (n_in >= 2 && in_sizes[0] == FF * UU && in_sizes[1] == BB * FF * TT) {
        const float* t = x; x = w; w = t;
    }
    float* out = (float*)d_out;

    prep_w_kernel<<<131072 / 256, 256>>>(w);
    transpose_w_kernel<<<dim3(UU / 32, FF / 32), dim3(32, 8)>>>(w);
    transpose_x_kernel<<<dim3(TT / 32, FF / 32, BB), dim3(32, 8)>>>(x);

    cudaFuncSetAttribute(snn_mma_gemm, cudaFuncAttributeMaxDynamicSharedMemorySize,
                         SMEM_TOTAL);
    snn_mma_gemm<<<dim3(UU / CTA_M, BB), NTHREADS, SMEM_TOTAL>>>(x, out);

    fixup_kernel<<<296, FIX_WARPS * 32>>>(out);
}

// round 9
// speedup vs baseline: 1.3977x; 1.1849x over previous
#include <cuda_runtime.h>
#include <cstdint>
#include <cstddef>

// ---------------- problem constants ----------------
#define BB 128
#define FF 512
#define TT 256
#define UU 1024

// ---------------- GEMM tiling ----------------
#define CTA_M 128
#define CTA_N 128
#define KC    32            // k per chunk (4 ksteps of 8)
#define NCHUNK (FF / KC)    // 16
#define NTHREADS 256        // 8 warps: 2(M) x 4(N), warp tile 64x32

#define FLAG_DELTA 4e-3f    // proven in R6
#define EXACT_BAND 5e-5
#define FLAG_CAP   (1u << 20)

// ---------------- scratch (device globals) ----------------
__device__ float g_a_perm[(size_t)64 * 64 * 32 * 4];   // W fragment-permuted fp32
__device__ float g_wt[(size_t)UU * FF];                // W^T  [U][F]
__device__ float g_xt[(size_t)BB * TT * FF];           // X^T  [B][T][F] (written by GEMM)
__device__ unsigned int g_flag_count;
__device__ unsigned int g_flag_list[FLAG_CAP];         // b[18:25)|u[8:18)|t[0:8)

// ---------------- helpers ----------------
__device__ __forceinline__ void cp16(uint32_t dst, const void* src) {
    asm volatile("cp.async.cg.shared.global [%0], [%1], 16;" :: "r"(dst), "l"(src));
}
__device__ __forceinline__ void cp_commit() { asm volatile("cp.async.commit_group;"); }
__device__ __forceinline__ void cp_wait1() { asm volatile("cp.async.wait_group 1;"); }
__device__ __forceinline__ void cp_wait0() { asm volatile("cp.async.wait_group 0;"); }

__device__ __forceinline__ void mma_tf32(float* c, const float4& a, const float2& b) {
    asm volatile(
        "mma.sync.aligned.m16n8k8.row.col.f32.tf32.tf32.f32 "
        "{%0,%1,%2,%3}, {%4,%5,%6,%7}, {%8,%9}, {%0,%1,%2,%3};"
        : "+f"(c[0]), "+f"(c[1]), "+f"(c[2]), "+f"(c[3])
        : "r"(__float_as_uint(a.x)), "r"(__float_as_uint(a.y)),
          "r"(__float_as_uint(a.z)), "r"(__float_as_uint(a.w)),
          "r"(__float_as_uint(b.x)), "r"(__float_as_uint(b.y)));
}

// ---------------- pre-pass: fragment-permute W (fp32) ----------------
__global__ __launch_bounds__(256)
void prep_w_kernel(const float* __restrict__ w) {
    const int idx = blockIdx.x * 256 + threadIdx.x;     // < 131072
    const int lane = idx & 31;
    const int mc   = (idx >> 5) & 63;
    const int kc   = idx >> 11;
    const int m = mc * 16 + (lane >> 2);
    const int k = kc * 8 + (lane & 3);
    float4 v;
    v.x = w[(size_t)k * UU + m];
    v.y = w[(size_t)k * UU + m + 8];
    v.z = w[(size_t)(k + 4) * UU + m];
    v.w = w[(size_t)(k + 4) * UU + m + 8];
    ((float4*)g_a_perm)[idx] = v;
    if (idx == 0) g_flag_count = 0;
}

__global__ __launch_bounds__(256)
void transpose_w_kernel(const float* __restrict__ w) {  // [F][U] -> [U][F]
    __shared__ float tile[32][33];
    const int u0 = blockIdx.x * 32, f0 = blockIdx.y * 32;
    const int tx = threadIdx.x, ty = threadIdx.y;       // 32 x 8
#pragma unroll
    for (int r = 0; r < 32; r += 8)
        tile[ty + r][tx] = w[(size_t)(f0 + ty + r) * UU + u0 + tx];
    __syncthreads();
#pragma unroll
    for (int r = 0; r < 32; r += 8)
        g_wt[(size_t)(u0 + ty + r) * FF + f0 + tx] = tile[tx][ty + r];
}

// ---------------- GEMM ----------------
// smem: A 2 x 16KB | B 2 x (32 rows x 136 floats = 17408B)
#define A_OFF      0
#define A_STAGE    16384
#define B_OFF      32768
#define B_STAGE    17408
#define B_ROWF     136
#define SMEM_TOTAL (32768 + 2 * B_STAGE)   // 67584

__global__ __launch_bounds__(NTHREADS, 2)
void snn_mma_gemm(const float* __restrict__ x, float* __restrict__ out) {
    extern __shared__ __align__(1024) char smem[];
    const uint32_t sb = (uint32_t)__cvta_generic_to_shared(smem);

    const int tid  = threadIdx.x;
    const int lane = tid & 31;
    const int wid  = tid >> 5;
    const int wm   = wid & 1;        // 2 warps along M (64 rows each)
    const int wn   = wid >> 1;       // 4 warps along N (32 cols each)
    const int nx   = blockIdx.x;     // t tile (2)
    const int mx   = blockIdx.y;     // m tile (8)
    const int b    = blockIdx.z;
    const int t0   = nx * CTA_N;
    const int mc0  = mx * 8;

    const float* xb = x + (size_t)b * FF * TT;

    auto issue = [&](int c, int s) {
        const uint32_t ast = sb + A_OFF + s * A_STAGE;
#pragma unroll
        for (int j = 0; j < 4; j++) {        // A: 1024 x 16B
            const int o = tid + j * 256;
            const int kt = o >> 8;
            const int off = o & 255;
            const size_t srcf = ((size_t)(c * 4 + kt) * 64 + mc0) * 128 + (size_t)off * 4;
            cp16(ast + o * 16, g_a_perm + srcf);
        }
        const uint32_t bst = sb + B_OFF + s * B_STAGE;
#pragma unroll
        for (int j = 0; j < 4; j++) {        // B: 32 rows x 512B (pad to 544B)
            const int o = tid + j * 256;
            const int row = o >> 5;
            const int col = o & 31;
            cp16(bst + row * 544 + col * 16,
                 xb + ((size_t)(c * KC + row)) * TT + t0 + col * 4);
        }
        cp_commit();
    };

    float acc[4][4][4];
#pragma unroll
    for (int mt = 0; mt < 4; mt++)
#pragma unroll
        for (int nt = 0; nt < 4; nt++)
#pragma unroll
            for (int q = 0; q < 4; q++) acc[mt][nt][q] = 0.0f;

    issue(0, 0);
    issue(1, 1);

#pragma unroll 1
    for (int c = 0; c < NCHUNK; c++) {
        if (c == NCHUNK - 1) cp_wait0(); else cp_wait1();
        __syncthreads();

        const int s = c & 1;
        const float*  rawB = (const float*)(smem + B_OFF + s * B_STAGE);
        const float4* As   = (const float4*)(smem + A_OFF + s * A_STAGE);

        // ---- fused X transpose: CTA mx == (c & 7) writes this tile to g_xt ----
        if (mx == (c & 7) && tid < CTA_N) {
            const int n = tid;               // local t index
            float* orow = g_xt + ((size_t)b * TT + t0 + n) * FF + c * KC;
            float4 v;
#pragma unroll
            for (int kq = 0; kq < 8; kq++) {
                v.x = rawB[(kq * 4 + 0) * B_ROWF + n];
                v.y = rawB[(kq * 4 + 1) * B_ROWF + n];
                v.z = rawB[(kq * 4 + 2) * B_ROWF + n];
                v.w = rawB[(kq * 4 + 3) * B_ROWF + n];
                *(float4*)(orow + kq * 4) = v;
            }
        }

#pragma unroll
        for (int kt = 0; kt < 4; kt++) {
            float4 fa[4];
            float2 fb[4];
#pragma unroll
            for (int mt = 0; mt < 4; mt++)
                fa[mt] = As[(kt * 8 + wm * 4 + mt) * 32 + lane];
            const int kb = kt * 8 + (lane & 3);
            const int nb = lane >> 2;
#pragma unroll
            for (int nt = 0; nt < 4; nt++) {
                const int n = wn * 32 + nt * 8 + nb;
                fb[nt].x = rawB[kb * B_ROWF + n];          // HW truncates to tf32
                fb[nt].y = rawB[(kb + 4) * B_ROWF + n];
            }
#pragma unroll
            for (int mt = 0; mt < 4; mt++)
#pragma unroll
                for (int nt = 0; nt < 4; nt++)
                    mma_tf32(acc[mt][nt], fa[mt], fb[nt]);
        }

        __syncthreads();
        if (c + 2 < NCHUNK) issue(c + 2, s);
    }

    // ---- epilogue: threshold + flag + store ----
    const int m_base = mx * CTA_M + wm * 64 + (lane >> 2);
    const int t_base = t0 + wn * 32 + (lane & 3) * 2;
#pragma unroll
    for (int mt = 0; mt < 4; mt++) {
#pragma unroll
        for (int nt = 0; nt < 4; nt++) {
            const int m = m_base + mt * 16;
            const int t = t_base + nt * 8;
#pragma unroll
            for (int h = 0; h < 2; h++) {
                const int mm = m + h * 8;
                const float v0 = acc[mt][nt][h * 2 + 0];
                const float v1 = acc[mt][nt][h * 2 + 1];
                float2 r;
                r.x = v0 > 1.0f ? 1.0f : 0.0f;
                r.y = v1 > 1.0f ? 1.0f : 0.0f;
                *(float2*)(out + ((size_t)b * UU + mm) * TT + t) = r;
                if (fabsf(v0 - 1.0f) < FLAG_DELTA) {
                    unsigned idx = atomicAdd(&g_flag_count, 1u);
                    if (idx < FLAG_CAP)
                        g_flag_list[idx] = ((unsigned)b << 18) | ((unsigned)mm << 8) | (unsigned)t;
                }
                if (fabsf(v1 - 1.0f) < FLAG_DELTA) {
                    unsigned idx = atomicAdd(&g_flag_count, 1u);
                    if (idx < FLAG_CAP)
                        g_flag_list[idx] = ((unsigned)b << 18) | ((unsigned)mm << 8) | (unsigned)(t + 1);
                }
            }
        }
    }
}

// ---------------- two-tier fixup ----------------
#define FIX_WARPS 8
__global__ __launch_bounds__(FIX_WARPS * 32)
void fixup_kernel(float* __restrict__ out) {
    __shared__ float ws[FIX_WARPS][FF];
    __shared__ float xs[FIX_WARPS][FF];
    const unsigned n = min(g_flag_count, (unsigned)FLAG_CAP);
    const int lane = threadIdx.x & 31;
    const int wrp  = threadIdx.x >> 5;
    const unsigned gw = blockIdx.x * FIX_WARPS + wrp;
    const unsigned nw = gridDim.x * FIX_WARPS;
    for (unsigned i = gw; i < n; i += nw) {
        const unsigned code = g_flag_list[i];
        const int b = code >> 18;
        const int u = (code >> 8) & 1023;
        const int t = code & 255;
        const float4* wr = (const float4*)(g_wt + (size_t)u * FF);
        const float4* xr = (const float4*)(g_xt + ((size_t)b * TT + t) * FF);
        double s = 0.0;
        float4 wa[4], xa[4];
#pragma unroll
        for (int j = 0; j < 4; j++) {
            wa[j] = wr[lane + j * 32];
            xa[j] = xr[lane + j * 32];
            s += (double)wa[j].x * (double)xa[j].x;
            s += (double)wa[j].y * (double)xa[j].y;
            s += (double)wa[j].z * (double)xa[j].z;
            s += (double)wa[j].w * (double)xa[j].w;
        }
#pragma unroll
        for (int o = 16; o > 0; o >>= 1)
            s += __shfl_xor_sync(0xFFFFFFFFu, s, o);
        if (fabs(s - 1.0) > EXACT_BAND) {
            if (lane == 0)
                out[((size_t)b * UU + u) * TT + t] = (s > 1.0) ? 1.0f : 0.0f;
        } else {
#pragma unroll
            for (int j = 0; j < 4; j++) {
                const int f = 4 * (lane + j * 32);
                *(float4*)&ws[wrp][f] = wa[j];
                *(float4*)&xs[wrp][f] = xa[j];
            }
            __syncwarp();
            if (lane == 0) {
                float acc = 0.0f;                  // exact sequential fp32 chain
#pragma unroll 16
                for (int f = 0; f < FF; f++)
                    acc = __fmaf_rn(ws[wrp][f], xs[wrp][f], acc);
                out[((size_t)b * UU + u) * TT + t] = acc > 1.0f ? 1.0f : 0.0f;
            }
            __syncwarp();
        }
    }
}

// ---------------- host side ----------------
extern "C" void kernel_launch(void* const* d_in, const int* in_sizes, int n_in,
                              void* d_out, int out_size) {
    const float* x = (const float*)d_in[0];   // [B, F, T]
    const float* w = (const float*)d_in[1];   // [F, U]
    if (n_in >= 2 && in_sizes[0] == FF * UU && in_sizes[1] == BB * FF * TT) {
        const float* t = x; x = w; w = t;
    }
    float* out = (float*)d_out;

    prep_w_kernel<<<131072 / 256, 256>>>(w);
    transpose_w_kernel<<<dim3(UU / 32, FF / 32), dim3(32, 8)>>>(w);

    cudaFuncSetAttribute(snn_mma_gemm, cudaFuncAttributeMaxDynamicSharedMemorySize,
                         SMEM_TOTAL);
    snn_mma_gemm<<<dim3(TT / CTA_N, UU / CTA_M, BB), NTHREADS, SMEM_TOTAL>>>(x, out);

    fixup_kernel<<<592, FIX_WARPS * 32>>>(out);
}